// round 2
// baseline (speedup 1.0000x reference)
#include <cuda_runtime.h>
#include <math.h>

// Problem constants
#define HH 128
#define WW 128
#define BATCH 2
#define CFEAT 128
#define PLANE (HH * WW)

typedef unsigned long long ull;

// ---------------------------------------------------------------------------
// f32x2 packed-FMA helpers (SASS FFMA2 — 2x fp32 rate, PTX-only)
// ---------------------------------------------------------------------------
__device__ __forceinline__ void fma2(ull& d, ull a, ull b) {
    asm("fma.rn.f32x2 %0, %1, %2, %3;" : "=l"(d) : "l"(a), "l"(b), "l"(d));
}
__device__ __forceinline__ ull pack2(float lo, float hi) {
    ull r;
    asm("mov.b64 %0, {%1, %2};" : "=l"(r) : "f"(lo), "f"(hi));
    return r;
}
__device__ __forceinline__ void unpack2(ull v, float& lo, float& hi) {
    asm("mov.b64 {%0, %1}, %2;" : "=f"(lo), "=f"(hi) : "l"(v));
}

// ---------------------------------------------------------------------------
// Scratch (device globals; no allocation allowed)
// ---------------------------------------------------------------------------
__device__ float g_tmp1[BATCH * 64 * PLANE];      // conv1 out  (B,64,H,W)
__device__ float g_off [BATCH * 18 * PLANE];      // offsets    (B,18,H,W)
__device__ float g_tmp2[BATCH * CFEAT * PLANE];   // deform out (B,128,H,W)
__device__ float g_tmp3[BATCH * 64 * PLANE];      // fh conv1   (B,64,H,W)
__device__ float g_dwt [9 * CFEAT * CFEAT];       // dweight transposed [k][c][o]

// ---------------------------------------------------------------------------
// Transpose deform weights: dweight (O=128, C=128, 3,3) -> dwt[k][c][o]
// ---------------------------------------------------------------------------
__global__ void wt_transpose_kernel(const float* __restrict__ dw) {
    int t = blockIdx.x * blockDim.x + threadIdx.x;
    if (t >= CFEAT * CFEAT * 9) return;
    int o  = t / (CFEAT * 9);
    int r  = t % (CFEAT * 9);
    int c  = r / 9;
    int kk = r % 9;
    g_dwt[(kk * CFEAT + c) * CFEAT + o] = dw[t];
}

// ---------------------------------------------------------------------------
// 3x3 SAME conv, Cout = 64, f32x2 inner product.
// Block: 32(w) x 4(h) pixels, all 64 out channels. 256 threads:
//   wx = tid&31 (pixel w), og = tid>>5 (8 groups of 8 out channels)
// Register tile per thread: 4(h) x 8(o), accumulated as 4x4 f32x2 pairs.
// Weights staged o-contiguous (natural f32x2 pairs over o); input pixel
// duplicated in registers via mov.b64 {v,v}.
// ---------------------------------------------------------------------------
template <int CINA, int CINB, bool RELU>
__global__ __launch_bounds__(256)
void conv3x3_c64_kernel(const float* __restrict__ inA, const float* __restrict__ inB,
                        const float* __restrict__ wgt, const float* __restrict__ bias,
                        float* __restrict__ out) {
    constexpr int CIN = CINA + CINB;
    constexpr int CB = 4;
    __shared__ float s_in[CB][6][34];
    __shared__ float s_w[CB][9][64];   // [cc][kk][o]  -- o contiguous

    const int tid = threadIdx.x;
    const int wx = tid & 31;
    const int og = tid >> 5;
    const int w0 = blockIdx.x * 32;
    const int h0 = blockIdx.y * 4;
    const int b  = blockIdx.z;

    ull acc2[4][4];
#pragma unroll
    for (int i = 0; i < 4; i++)
#pragma unroll
        for (int j = 0; j < 4; j++) acc2[i][j] = 0ULL;

    for (int c0 = 0; c0 < CIN; c0 += CB) {
        // ---- stage input patch (CB channels, 6 rows x 34 cols, zero-padded)
        for (int i = tid; i < CB * 6 * 34; i += 256) {
            int cc  = i / 204;
            int rem = i % 204;
            int r   = rem / 34;
            int col = rem % 34;
            int c = c0 + cc;
            int y = h0 - 1 + r;
            int x = w0 - 1 + col;
            float v = 0.f;
            if (c < CIN && y >= 0 && y < HH && x >= 0 && x < WW) {
                v = (c < CINA) ? inA[((b * CINA + c) * HH + y) * WW + x]
                               : inB[((b * CINB + (c - CINA)) * HH + y) * WW + x];
            }
            s_in[cc][r][col] = v;
        }
        // ---- stage weights o-contiguous: s_w[cc][kk][o]
        for (int i = tid; i < CB * 9 * 64; i += 256) {
            int o   = i & 63;
            int kk  = (i >> 6) % 9;
            int cc  = i / 576;
            int c = c0 + cc;
            s_w[cc][kk][o] = (c < CIN) ? wgt[(o * CIN + c) * 9 + kk] : 0.f;
        }
        __syncthreads();

#pragma unroll
        for (int cc = 0; cc < CB; cc++) {
#pragma unroll
            for (int kh = 0; kh < 3; kh++) {
#pragma unroll
                for (int kw = 0; kw < 3; kw++) {
                    const ulonglong2* bp =
                        (const ulonglong2*)&s_w[cc][kh * 3 + kw][og * 8];
                    ulonglong2 b01 = bp[0];
                    ulonglong2 b23 = bp[1];
                    ull bb[4] = {b01.x, b01.y, b23.x, b23.y};
#pragma unroll
                    for (int i = 0; i < 4; i++) {
                        float v = s_in[cc][i + kh][wx + kw];
                        ull a = pack2(v, v);
#pragma unroll
                        for (int j = 0; j < 4; j++) fma2(acc2[i][j], a, bb[j]);
                    }
                }
            }
        }
        __syncthreads();
    }

    // epilogue: lanes of acc2[i][j] are o = og*8 + 2j (+1)
#pragma unroll
    for (int j = 0; j < 4; j++) {
        int o0 = og * 8 + 2 * j;
        float b0 = bias[o0];
        float b1 = bias[o0 + 1];
#pragma unroll
        for (int i = 0; i < 4; i++) {
            float lo, hi;
            unpack2(acc2[i][j], lo, hi);
            float v0 = lo + b0;
            float v1 = hi + b1;
            if (RELU) { v0 = fmaxf(v0, 0.f); v1 = fmaxf(v1, 0.f); }
            out[((b * 64 + o0)     * HH + (h0 + i)) * WW + w0 + wx] = v0;
            out[((b * 64 + o0 + 1) * HH + (h0 + i)) * WW + w0 + wx] = v1;
        }
    }
}

// ---------------------------------------------------------------------------
// 3x3 SAME conv, CIN=64, small Cout (<=18), optional residual add.
// Block: 32(w) x 8(h) pixels; each thread computes all COUT channels of 1 px.
// ---------------------------------------------------------------------------
template <int COUT, bool RES>
__global__ __launch_bounds__(256)
void conv3x3_small_kernel(const float* __restrict__ in, const float* __restrict__ wgt,
                          const float* __restrict__ bias, const float* __restrict__ res,
                          float* __restrict__ out) {
    constexpr int CIN = 64;
    constexpr int CB = 4;
    __shared__ float s_in[CB][10][34];
    __shared__ float s_w[CB][COUT * 9];

    const int tid = threadIdx.x;
    const int wx = tid & 31;
    const int hy = tid >> 5;
    const int w0 = blockIdx.x * 32;
    const int h0 = blockIdx.y * 8;
    const int b  = blockIdx.z;

    float acc[COUT];
#pragma unroll
    for (int o = 0; o < COUT; o++) acc[o] = 0.f;

    for (int c0 = 0; c0 < CIN; c0 += CB) {
        for (int i = tid; i < CB * 10 * 34; i += 256) {
            int cc  = i / 340;
            int rem = i % 340;
            int r   = rem / 34;
            int col = rem % 34;
            int y = h0 - 1 + r;
            int x = w0 - 1 + col;
            float v = 0.f;
            if (y >= 0 && y < HH && x >= 0 && x < WW)
                v = in[((b * CIN + c0 + cc) * HH + y) * WW + x];
            s_in[cc][r][col] = v;
        }
        for (int i = tid; i < CB * COUT * 9; i += 256) {
            int cc  = i / (COUT * 9);
            int rem = i % (COUT * 9);
            int o   = rem / 9;
            int kk  = rem % 9;
            s_w[cc][rem] = wgt[(o * CIN + (c0 + cc)) * 9 + kk];
        }
        __syncthreads();

#pragma unroll
        for (int cc = 0; cc < CB; cc++) {
#pragma unroll
            for (int kh = 0; kh < 3; kh++) {
#pragma unroll
                for (int kw = 0; kw < 3; kw++) {
                    float iv = s_in[cc][hy + kh][wx + kw];
#pragma unroll
                    for (int o = 0; o < COUT; o++)
                        acc[o] += iv * s_w[cc][o * 9 + kh * 3 + kw];
                }
            }
        }
        __syncthreads();
    }

#pragma unroll
    for (int o = 0; o < COUT; o++) {
        float v = acc[o] + bias[o];
        int oi = ((b * COUT + o) * HH + (h0 + hy)) * WW + w0 + wx;
        if (RES) v += res[oi];
        out[oi] = v;
    }
}

// ---------------------------------------------------------------------------
// Deformable 3x3 conv v2: feat (B,128,H,W), offsets (B,18,H,W), dwt[k][c][o].
// Block = 64 pixels (one w-half-row) x all 128 out channels. 256 threads.
// Per k: stage w[k] (128x128, o-contiguous) in smem, bilinear-gather samples
// into smem as DUPLICATED float2 pairs {v,v}, then a 128x128x64 GEMM with
// f32x2 packed FMAs: per thread 4 px (dup A) x 4 o-pairs (natural B),
// 16 fma2 per c = 32 FMA, 4 LDS.128 per c.
// Dynamic smem = 149,504 B -> 1 CTA/SM.
// ---------------------------------------------------------------------------
__global__ __launch_bounds__(256)
void deform_kernel(const float* __restrict__ feat, const float* __restrict__ offs,
                   const float* __restrict__ dbias, float* __restrict__ out) {
    extern __shared__ float smem[];
    float*  s_wk   = smem;                       // 16384 floats [c][o]
    float2* s_samp = (float2*)(smem + 16384);    // [c][64] dup pairs (16384 floats)
    float*  s_wt   = smem + 32768;               // [k][px][4] 2304 floats
    int*    s_idx  = (int*)(smem + 35072);       // [k][px][4] 2304 ints

    const int tid = threadIdx.x;
    const int w0 = blockIdx.x * 64;
    const int h  = blockIdx.y;
    const int b  = blockIdx.z;

    // ---- precompute bilinear corners per (k, px)
    for (int task = tid; task < 576; task += 256) {
        int k  = task >> 6;
        int px = task & 63;
        int w = w0 + px;
        float offy = offs[((b * 18 + 2 * k)     * HH + h) * WW + w];
        float offx = offs[((b * 18 + 2 * k + 1) * HH + h) * WW + w];
        float fy = (float)(h + k / 3 - 1) + offy;
        float fx = (float)(w + k % 3 - 1) + offx;
        float y0f = floorf(fy), x0f = floorf(fx);
        float ly = fy - y0f, lx = fx - x0f;
        int y0 = (int)y0f, x0 = (int)x0f;
        float wts[4] = {(1.f - ly) * (1.f - lx), (1.f - ly) * lx,
                        ly * (1.f - lx),          ly * lx};
        int ys[4] = {y0, y0, y0 + 1, y0 + 1};
        int xs[4] = {x0, x0 + 1, x0, x0 + 1};
#pragma unroll
        for (int c4 = 0; c4 < 4; c4++) {
            bool valid = (ys[c4] >= 0) && (ys[c4] < HH) && (xs[c4] >= 0) && (xs[c4] < WW);
            s_idx[(k * 64 + px) * 4 + c4] = valid ? (ys[c4] * WW + xs[c4]) : 0;
            s_wt [(k * 64 + px) * 4 + c4] = valid ? wts[c4] : 0.f;
        }
    }
    __syncthreads();

    ull acc2[4][4];
#pragma unroll
    for (int i = 0; i < 4; i++)
#pragma unroll
        for (int j = 0; j < 4; j++) acc2[i][j] = 0ULL;

    const int gpx = tid & 63;   // gather: pixel
    const int gog = tid >> 6;   // gather: channel group (0..3)
    const int pxg = tid & 15;   // GEMM: 16 groups of 4 pixels
    const int og  = tid >> 4;   // GEMM: 16 groups of 8 out channels
    const float* fbase = feat + (size_t)b * CFEAT * PLANE;

    for (int k = 0; k < 9; k++) {
        // ---- stage weights for this k (contiguous [c][o], float4)
        const float4* wk4  = (const float4*)(g_dwt + k * CFEAT * CFEAT);
        float4*       swk4 = (float4*)s_wk;
#pragma unroll
        for (int i = 0; i < 16; i++) swk4[tid + 256 * i] = wk4[tid + 256 * i];

        // ---- bilinear gather: thread px=gpx, channels gog*32 + j
        const int4   iv = *(const int4*)&s_idx[(k * 64 + gpx) * 4];
        const float4 qv = *(const float4*)&s_wt[(k * 64 + gpx) * 4];
#pragma unroll 8
        for (int j = 0; j < 32; j++) {
            int c = gog * 32 + j;
            const float* fc = fbase + (size_t)c * PLANE;
            float v = qv.x * fc[iv.x] + qv.y * fc[iv.y] + qv.z * fc[iv.z] + qv.w * fc[iv.w];
            s_samp[c * 64 + gpx] = make_float2(v, v);
        }
        __syncthreads();

        // ---- 128(o) x 64(px) x 128(c) GEMM slice with f32x2
#pragma unroll 4
        for (int c = 0; c < CFEAT; c++) {
            const ulonglong2* ap = (const ulonglong2*)(s_samp + c * 64 + pxg * 4);
            ulonglong2 a01 = ap[0];
            ulonglong2 a23 = ap[1];
            const ulonglong2* bp = (const ulonglong2*)(s_wk + c * CFEAT + og * 8);
            ulonglong2 b01 = bp[0];
            ulonglong2 b23 = bp[1];
            ull a[4]  = {a01.x, a01.y, a23.x, a23.y};
            ull bb[4] = {b01.x, b01.y, b23.x, b23.y};
#pragma unroll
            for (int i = 0; i < 4; i++)
#pragma unroll
                for (int j = 0; j < 4; j++) fma2(acc2[i][j], a[i], bb[j]);
        }
        __syncthreads();
    }

    // ---- epilogue: acc2[i][j] lanes are o = og*8 + 2j (+1), px = pxg*4 + i
    float accf[4][8];
#pragma unroll
    for (int i = 0; i < 4; i++)
#pragma unroll
        for (int j = 0; j < 4; j++)
            unpack2(acc2[i][j], accf[i][2 * j], accf[i][2 * j + 1]);

#pragma unroll
    for (int oo = 0; oo < 8; oo++) {
        int o = og * 8 + oo;
        float bv = dbias[o];
        float4 r;
        r.x = accf[0][oo] + bv;
        r.y = accf[1][oo] + bv;
        r.z = accf[2][oo] + bv;
        r.w = accf[3][oo] + bv;
        *(float4*)&out[(((size_t)b * CFEAT + o) * HH + h) * WW + w0 + pxg * 4] = r;
    }
}

// ---------------------------------------------------------------------------
// Launch
// ---------------------------------------------------------------------------
extern "C" void kernel_launch(void* const* d_in, const int* in_sizes, int n_in,
                              void* d_out, int out_size) {
    const float* feat    = (const float*)d_in[0];
    const float* flow    = (const float*)d_in[1];
    const float* off_w1  = (const float*)d_in[2];
    const float* off_b1  = (const float*)d_in[3];
    const float* off_w2  = (const float*)d_in[4];
    const float* off_b2  = (const float*)d_in[5];
    const float* dweight = (const float*)d_in[6];
    const float* dbias   = (const float*)d_in[7];
    const float* fh_w1   = (const float*)d_in[8];
    const float* fh_b1   = (const float*)d_in[9];
    const float* fh_w2   = (const float*)d_in[10];
    const float* fh_b2   = (const float*)d_in[11];
    float* out = (float*)d_out;

    float *tmp1, *off, *tmp2, *tmp3;
    cudaGetSymbolAddress((void**)&tmp1, g_tmp1);
    cudaGetSymbolAddress((void**)&off,  g_off);
    cudaGetSymbolAddress((void**)&tmp2, g_tmp2);
    cudaGetSymbolAddress((void**)&tmp3, g_tmp3);

    const int DEFORM_SMEM = (16384 + 16384 + 2304 + 2304) * 4;  // 149504 B
    cudaFuncSetAttribute(deform_kernel, cudaFuncAttributeMaxDynamicSharedMemorySize,
                         DEFORM_SMEM);

    // 1. transpose deform weights -> [k][c][o]
    wt_transpose_kernel<<<(CFEAT * CFEAT * 9 + 255) / 256, 256>>>(dweight);

    // 2. conv1: concat(feat, flow) (130ch) -> 64ch, relu
    conv3x3_c64_kernel<128, 2, true><<<dim3(4, 32, BATCH), 256>>>(
        feat, flow, off_w1, off_b1, tmp1);

    // 3. conv2: 64 -> 18 (offsets)
    conv3x3_small_kernel<18, false><<<dim3(4, 16, BATCH), 256>>>(
        tmp1, off_w2, off_b2, nullptr, off);

    // 4. deformable conv: feat + offsets -> 128ch
    deform_kernel<<<dim3(2, 128, BATCH), 256, DEFORM_SMEM>>>(feat, off, dbias, tmp2);

    // 5. fh conv1: 128 -> 64, relu
    conv3x3_c64_kernel<128, 0, true><<<dim3(4, 32, BATCH), 256>>>(
        tmp2, tmp2, fh_w1, fh_b1, tmp3);

    // 6. fh conv2: 64 -> 2, + flow residual
    conv3x3_small_kernel<2, true><<<dim3(4, 16, BATCH), 256>>>(
        tmp3, fh_w2, fh_b2, flow, out);
}

// round 3
// speedup vs baseline: 1.2945x; 1.2945x over previous
#include <cuda_runtime.h>
#include <math.h>

// Problem constants
#define HH 128
#define WW 128
#define BATCH 2
#define CFEAT 128
#define PLANE (HH * WW)

typedef unsigned long long ull;

// ---------------------------------------------------------------------------
// f32x2 packed-FMA helpers (SASS FFMA2 — PTX-only)
// ---------------------------------------------------------------------------
__device__ __forceinline__ void fma2(ull& d, ull a, ull b) {
    asm("fma.rn.f32x2 %0, %1, %2, %3;" : "=l"(d) : "l"(a), "l"(b), "l"(d));
}
__device__ __forceinline__ ull pack2(float lo, float hi) {
    ull r;
    asm("mov.b64 %0, {%1, %2};" : "=l"(r) : "f"(lo), "f"(hi));
    return r;
}
__device__ __forceinline__ void unpack2(ull v, float& lo, float& hi) {
    asm("mov.b64 {%0, %1}, %2;" : "=f"(lo), "=f"(hi) : "l"(v));
}

// ---------------------------------------------------------------------------
// Scratch (device globals; no allocation allowed)
// ---------------------------------------------------------------------------
__device__ float g_tmp1[BATCH * 64 * PLANE];      // conv1 out  (B,64,H,W)
__device__ float g_off [BATCH * 18 * PLANE];      // offsets    (B,18,H,W)
__device__ float g_tmp2[BATCH * CFEAT * PLANE];   // deform out (B,128,H,W)
__device__ float g_tmp3[BATCH * 64 * PLANE];      // fh conv1   (B,64,H,W)
__device__ float g_dwt [9 * CFEAT * CFEAT];       // dweight transposed [k][c][o]
__device__ float g_w1t [9 * 130 * 64];            // off_w1 transposed [kk][c][o]
__device__ float g_w3t [9 * 128 * 64];            // fh_w1  transposed [kk][c][o]

// ---------------------------------------------------------------------------
// Transpose deform weights: dweight (O=128, C=128, 3,3) -> dwt[k][c][o]
// ---------------------------------------------------------------------------
__global__ void wt_transpose_kernel(const float* __restrict__ dw) {
    int t = blockIdx.x * blockDim.x + threadIdx.x;
    if (t >= CFEAT * CFEAT * 9) return;
    int o  = t / (CFEAT * 9);
    int r  = t % (CFEAT * 9);
    int c  = r / 9;
    int kk = r % 9;
    g_dwt[(kk * CFEAT + c) * CFEAT + o] = dw[t];
}

// Transpose conv weights: w (64, CIN, 3,3) -> dst[(kk*CIN + c)*64 + o]
__global__ void conv_wt_transpose_kernel(const float* __restrict__ w,
                                         float* __restrict__ dst, int cin) {
    int t = blockIdx.x * blockDim.x + threadIdx.x;
    if (t >= 64 * cin * 9) return;
    int o  = t / (cin * 9);
    int r  = t % (cin * 9);
    int c  = r / 9;
    int kk = r % 9;
    dst[(kk * cin + c) * 64 + o] = w[t];
}

// ---------------------------------------------------------------------------
// 3x3 SAME conv, Cout = 64, f32x2 inner product, pre-transposed weights.
// Block: 32(w) x 4(h) pixels, all 64 out channels. 256 threads:
//   wx = tid&31 (pixel w), og = tid>>5 (8 groups of 8 out channels)
// ---------------------------------------------------------------------------
template <int CINA, int CINB, bool RELU>
__global__ __launch_bounds__(256)
void conv3x3_c64_kernel(const float* __restrict__ inA, const float* __restrict__ inB,
                        const float* __restrict__ wt, const float* __restrict__ bias,
                        float* __restrict__ out) {
    constexpr int CIN = CINA + CINB;
    constexpr int CB = 4;
    __shared__ float s_in[CB][6][34];
    __shared__ float s_w[CB][9][64];   // [cc][kk][o]  -- o contiguous

    const int tid = threadIdx.x;
    const int wx = tid & 31;
    const int og = tid >> 5;
    const int w0 = blockIdx.x * 32;
    const int h0 = blockIdx.y * 4;
    const int b  = blockIdx.z;

    ull acc2[4][4];
#pragma unroll
    for (int i = 0; i < 4; i++)
#pragma unroll
        for (int j = 0; j < 4; j++) acc2[i][j] = 0ULL;

    for (int c0 = 0; c0 < CIN; c0 += CB) {
        // ---- stage input patch (CB channels, 6 rows x 34 cols, zero-padded)
        for (int i = tid; i < CB * 6 * 34; i += 256) {
            int cc  = i / 204;
            int rem = i % 204;
            int r   = rem / 34;
            int col = rem % 34;
            int c = c0 + cc;
            int y = h0 - 1 + r;
            int x = w0 - 1 + col;
            float v = 0.f;
            if (c < CIN && y >= 0 && y < HH && x >= 0 && x < WW) {
                v = (c < CINA) ? inA[((b * CINA + c) * HH + y) * WW + x]
                               : inB[((b * CINB + (c - CINA)) * HH + y) * WW + x];
            }
            s_in[cc][r][col] = v;
        }
        // ---- stage weights from transposed buffer (coalesced: o fastest)
        for (int i = tid; i < CB * 9 * 64; i += 256) {
            int o   = i & 63;
            int kk  = (i >> 6) % 9;
            int cc  = i / 576;
            int c = c0 + cc;
            s_w[cc][kk][o] = (c < CIN) ? wt[(kk * CIN + c) * 64 + o] : 0.f;
        }
        __syncthreads();

#pragma unroll
        for (int cc = 0; cc < CB; cc++) {
#pragma unroll
            for (int kh = 0; kh < 3; kh++) {
#pragma unroll
                for (int kw = 0; kw < 3; kw++) {
                    const ulonglong2* bp =
                        (const ulonglong2*)&s_w[cc][kh * 3 + kw][og * 8];
                    ulonglong2 b01 = bp[0];
                    ulonglong2 b23 = bp[1];
                    ull bb[4] = {b01.x, b01.y, b23.x, b23.y};
#pragma unroll
                    for (int i = 0; i < 4; i++) {
                        float v = s_in[cc][i + kh][wx + kw];
                        ull a = pack2(v, v);
#pragma unroll
                        for (int j = 0; j < 4; j++) fma2(acc2[i][j], a, bb[j]);
                    }
                }
            }
        }
        __syncthreads();
    }

    // epilogue: lanes of acc2[i][j] are o = og*8 + 2j (+1)
#pragma unroll
    for (int j = 0; j < 4; j++) {
        int o0 = og * 8 + 2 * j;
        float b0 = bias[o0];
        float b1 = bias[o0 + 1];
#pragma unroll
        for (int i = 0; i < 4; i++) {
            float lo, hi;
            unpack2(acc2[i][j], lo, hi);
            float v0 = lo + b0;
            float v1 = hi + b1;
            if (RELU) { v0 = fmaxf(v0, 0.f); v1 = fmaxf(v1, 0.f); }
            out[((b * 64 + o0)     * HH + (h0 + i)) * WW + w0 + wx] = v0;
            out[((b * 64 + o0 + 1) * HH + (h0 + i)) * WW + w0 + wx] = v1;
        }
    }
}

// ---------------------------------------------------------------------------
// 3x3 SAME conv, CIN=64, small Cout (<=18), optional residual add.
// (round-1 known-good version)
// ---------------------------------------------------------------------------
template <int COUT, bool RES>
__global__ __launch_bounds__(256)
void conv3x3_small_kernel(const float* __restrict__ in, const float* __restrict__ wgt,
                          const float* __restrict__ bias, const float* __restrict__ res,
                          float* __restrict__ out) {
    constexpr int CIN = 64;
    constexpr int CB = 4;
    __shared__ float s_in[CB][10][34];
    __shared__ float s_w[CB][COUT * 9];

    const int tid = threadIdx.x;
    const int wx = tid & 31;
    const int hy = tid >> 5;
    const int w0 = blockIdx.x * 32;
    const int h0 = blockIdx.y * 8;
    const int b  = blockIdx.z;

    float acc[COUT];
#pragma unroll
    for (int o = 0; o < COUT; o++) acc[o] = 0.f;

    for (int c0 = 0; c0 < CIN; c0 += CB) {
        for (int i = tid; i < CB * 10 * 34; i += 256) {
            int cc  = i / 340;
            int rem = i % 340;
            int r   = rem / 34;
            int col = rem % 34;
            int y = h0 - 1 + r;
            int x = w0 - 1 + col;
            float v = 0.f;
            if (y >= 0 && y < HH && x >= 0 && x < WW)
                v = in[((b * CIN + c0 + cc) * HH + y) * WW + x];
            s_in[cc][r][col] = v;
        }
        for (int i = tid; i < CB * COUT * 9; i += 256) {
            int cc  = i / (COUT * 9);
            int rem = i % (COUT * 9);
            int o   = rem / 9;
            int kk  = rem % 9;
            s_w[cc][rem] = wgt[(o * CIN + (c0 + cc)) * 9 + kk];
        }
        __syncthreads();

#pragma unroll
        for (int cc = 0; cc < CB; cc++) {
#pragma unroll
            for (int kh = 0; kh < 3; kh++) {
#pragma unroll
                for (int kw = 0; kw < 3; kw++) {
                    float iv = s_in[cc][hy + kh][wx + kw];
#pragma unroll
                    for (int o = 0; o < COUT; o++)
                        acc[o] += iv * s_w[cc][o * 9 + kh * 3 + kw];
                }
            }
        }
        __syncthreads();
    }

#pragma unroll
    for (int o = 0; o < COUT; o++) {
        float v = acc[o] + bias[o];
        int oi = ((b * COUT + o) * HH + (h0 + hy)) * WW + w0 + wx;
        if (RES) v += res[oi];
        out[oi] = v;
    }
}

// ---------------------------------------------------------------------------
// Deformable 3x3 conv v3.
// Block = 128 pixels (one full row) x all 128 out channels. 256 threads.
// Per k: stage w[k] (128x128, o-contiguous) + bilinear-gathered samples
// (stored ONCE, no duplication) in smem, then 128x128x128 GEMM slice:
// per thread 8px x 8o, A dup'd into registers, f32x2 packed FMAs:
// per c-step: 4 LDS.128 (64B) + 8 packs + 32 fma2 = 64 FMA -> 1.0 B/FMA.
// Dynamic smem = 167,936 B -> 1 CTA/SM.
// ---------------------------------------------------------------------------
__global__ __launch_bounds__(256)
void deform_kernel(const float* __restrict__ feat, const float* __restrict__ offs,
                   const float* __restrict__ dbias, float* __restrict__ out) {
    extern __shared__ float smem[];
    float* s_wk   = smem;                        // 16384 floats [c][o]
    float* s_samp = smem + 16384;                // 16384 floats [c][px]
    float* s_wt   = smem + 32768;                // 4608 floats  [k][px][4]
    int*   s_idx  = (int*)(smem + 37376);        // 4608 ints    [k][px][4]

    const int tid = threadIdx.x;
    const int h  = blockIdx.y;
    const int b  = blockIdx.z;

    // ---- precompute bilinear corners per (k, px)
    for (int task = tid; task < 1152; task += 256) {
        int k  = task >> 7;
        int px = task & 127;
        float offy = offs[((b * 18 + 2 * k)     * HH + h) * WW + px];
        float offx = offs[((b * 18 + 2 * k + 1) * HH + h) * WW + px];
        float fy = (float)(h + k / 3 - 1) + offy;
        float fx = (float)(px + k % 3 - 1) + offx;
        float y0f = floorf(fy), x0f = floorf(fx);
        float ly = fy - y0f, lx = fx - x0f;
        int y0 = (int)y0f, x0 = (int)x0f;
        float wts[4] = {(1.f - ly) * (1.f - lx), (1.f - ly) * lx,
                        ly * (1.f - lx),          ly * lx};
        int ys[4] = {y0, y0, y0 + 1, y0 + 1};
        int xs[4] = {x0, x0 + 1, x0, x0 + 1};
#pragma unroll
        for (int c4 = 0; c4 < 4; c4++) {
            bool valid = (ys[c4] >= 0) && (ys[c4] < HH) && (xs[c4] >= 0) && (xs[c4] < WW);
            s_idx[(k * 128 + px) * 4 + c4] = valid ? (ys[c4] * WW + xs[c4]) : 0;
            s_wt [(k * 128 + px) * 4 + c4] = valid ? wts[c4] : 0.f;
        }
    }
    __syncthreads();

    ull acc2[8][4];
#pragma unroll
    for (int i = 0; i < 8; i++)
#pragma unroll
        for (int j = 0; j < 4; j++) acc2[i][j] = 0ULL;

    const int gpx = tid & 127;          // gather: pixel
    const int gc0 = (tid >> 7) * 64;    // gather: channel base (0 or 64)
    const int pxg = tid & 15;           // GEMM: 16 groups of 8 pixels
    const int og  = tid >> 4;           // GEMM: 16 groups of 8 out channels
    const float* fbase = feat + (size_t)b * CFEAT * PLANE;

    for (int k = 0; k < 9; k++) {
        // ---- stage weights for this k (contiguous [c][o], float4)
        const float4* wk4  = (const float4*)(g_dwt + k * CFEAT * CFEAT);
        float4*       swk4 = (float4*)s_wk;
#pragma unroll
        for (int i = 0; i < 16; i++) swk4[tid + 256 * i] = wk4[tid + 256 * i];

        // ---- bilinear gather: thread px=gpx, 64 channels starting at gc0
        const int4   iv = *(const int4*)&s_idx[(k * 128 + gpx) * 4];
        const float4 qv = *(const float4*)&s_wt[(k * 128 + gpx) * 4];
#pragma unroll 8
        for (int j = 0; j < 64; j++) {
            int c = gc0 + j;
            const float* fc = fbase + (size_t)c * PLANE;
            s_samp[c * 128 + gpx] =
                qv.x * fc[iv.x] + qv.y * fc[iv.y] + qv.z * fc[iv.z] + qv.w * fc[iv.w];
        }
        __syncthreads();

        // ---- 128(o) x 128(px) x 128(c) GEMM slice, 8px x 8o per thread
#pragma unroll 2
        for (int c = 0; c < CFEAT; c++) {
            const float4* ap = (const float4*)(s_samp + c * 128 + pxg * 8);
            float4 a0 = ap[0];
            float4 a1 = ap[1];
            const ulonglong2* bp = (const ulonglong2*)(s_wk + c * CFEAT + og * 8);
            ulonglong2 b01 = bp[0];
            ulonglong2 b23 = bp[1];
            ull bb[4] = {b01.x, b01.y, b23.x, b23.y};
            ull ad[8];
            ad[0] = pack2(a0.x, a0.x); ad[1] = pack2(a0.y, a0.y);
            ad[2] = pack2(a0.z, a0.z); ad[3] = pack2(a0.w, a0.w);
            ad[4] = pack2(a1.x, a1.x); ad[5] = pack2(a1.y, a1.y);
            ad[6] = pack2(a1.z, a1.z); ad[7] = pack2(a1.w, a1.w);
#pragma unroll
            for (int i = 0; i < 8; i++)
#pragma unroll
                for (int j = 0; j < 4; j++) fma2(acc2[i][j], ad[i], bb[j]);
        }
        __syncthreads();
    }

    // ---- epilogue: acc2[i][j] lanes are o = og*8 + 2j (+1), px = pxg*8 + i
#pragma unroll
    for (int j = 0; j < 4; j++) {
        int o0 = og * 8 + 2 * j;
        float bv0 = dbias[o0];
        float bv1 = dbias[o0 + 1];
        float lo[8], hi[8];
#pragma unroll
        for (int i = 0; i < 8; i++) unpack2(acc2[i][j], lo[i], hi[i]);
        float* p0 = &out[(((size_t)b * CFEAT + o0)     * HH + h) * WW + pxg * 8];
        float* p1 = &out[(((size_t)b * CFEAT + o0 + 1) * HH + h) * WW + pxg * 8];
        ((float4*)p0)[0] = make_float4(lo[0] + bv0, lo[1] + bv0, lo[2] + bv0, lo[3] + bv0);
        ((float4*)p0)[1] = make_float4(lo[4] + bv0, lo[5] + bv0, lo[6] + bv0, lo[7] + bv0);
        ((float4*)p1)[0] = make_float4(hi[0] + bv1, hi[1] + bv1, hi[2] + bv1, hi[3] + bv1);
        ((float4*)p1)[1] = make_float4(hi[4] + bv1, hi[5] + bv1, hi[6] + bv1, hi[7] + bv1);
    }
}

// ---------------------------------------------------------------------------
// Launch
// ---------------------------------------------------------------------------
extern "C" void kernel_launch(void* const* d_in, const int* in_sizes, int n_in,
                              void* d_out, int out_size) {
    const float* feat    = (const float*)d_in[0];
    const float* flow    = (const float*)d_in[1];
    const float* off_w1  = (const float*)d_in[2];
    const float* off_b1  = (const float*)d_in[3];
    const float* off_w2  = (const float*)d_in[4];
    const float* off_b2  = (const float*)d_in[5];
    const float* dweight = (const float*)d_in[6];
    const float* dbias   = (const float*)d_in[7];
    const float* fh_w1   = (const float*)d_in[8];
    const float* fh_b1   = (const float*)d_in[9];
    const float* fh_w2   = (const float*)d_in[10];
    const float* fh_b2   = (const float*)d_in[11];
    float* out = (float*)d_out;

    float *tmp1, *off, *tmp2, *tmp3, *w1t, *w3t;
    cudaGetSymbolAddress((void**)&tmp1, g_tmp1);
    cudaGetSymbolAddress((void**)&off,  g_off);
    cudaGetSymbolAddress((void**)&tmp2, g_tmp2);
    cudaGetSymbolAddress((void**)&tmp3, g_tmp3);
    cudaGetSymbolAddress((void**)&w1t,  g_w1t);
    cudaGetSymbolAddress((void**)&w3t,  g_w3t);

    const int DEFORM_SMEM = (16384 + 16384 + 4608 + 4608) * 4;  // 167936 B
    cudaFuncSetAttribute(deform_kernel, cudaFuncAttributeMaxDynamicSharedMemorySize,
                         DEFORM_SMEM);

    // 0. weight transposes
    wt_transpose_kernel<<<(CFEAT * CFEAT * 9 + 255) / 256, 256>>>(dweight);
    conv_wt_transpose_kernel<<<(64 * 130 * 9 + 255) / 256, 256>>>(off_w1, w1t, 130);
    conv_wt_transpose_kernel<<<(64 * 128 * 9 + 255) / 256, 256>>>(fh_w1, w3t, 128);

    // 1. conv1: concat(feat, flow) (130ch) -> 64ch, relu
    conv3x3_c64_kernel<128, 2, true><<<dim3(4, 32, BATCH), 256>>>(
        feat, flow, w1t, off_b1, tmp1);

    // 2. conv2: 64 -> 18 (offsets)
    conv3x3_small_kernel<18, false><<<dim3(4, 16, BATCH), 256>>>(
        tmp1, off_w2, off_b2, nullptr, off);

    // 3. deformable conv: feat + offsets -> 128ch
    deform_kernel<<<dim3(1, 128, BATCH), 256, DEFORM_SMEM>>>(feat, off, dbias, tmp2);

    // 4. fh conv1: 128 -> 64, relu
    conv3x3_c64_kernel<128, 0, true><<<dim3(4, 32, BATCH), 256>>>(
        tmp2, tmp2, w3t, fh_b1, tmp3);

    // 5. fh conv2: 64 -> 2, + flow residual
    conv3x3_small_kernel<2, true><<<dim3(4, 16, BATCH), 256>>>(
        tmp3, fh_w2, fh_b2, flow, out);
}

// round 4
// speedup vs baseline: 1.3235x; 1.0224x over previous
#include <cuda_runtime.h>
#include <math.h>

// Problem constants
#define HH 128
#define WW 128
#define BATCH 2
#define CFEAT 128
#define PLANE (HH * WW)

typedef unsigned long long ull;

// ---------------------------------------------------------------------------
// f32x2 packed-FMA helpers (SASS FFMA2 — PTX-only)
// ---------------------------------------------------------------------------
__device__ __forceinline__ void fma2(ull& d, ull a, ull b) {
    asm("fma.rn.f32x2 %0, %1, %2, %3;" : "=l"(d) : "l"(a), "l"(b), "l"(d));
}
__device__ __forceinline__ ull pack2(float lo, float hi) {
    ull r;
    asm("mov.b64 %0, {%1, %2};" : "=l"(r) : "f"(lo), "f"(hi));
    return r;
}
__device__ __forceinline__ void unpack2(ull v, float& lo, float& hi) {
    asm("mov.b64 {%0, %1}, %2;" : "=f"(lo), "=f"(hi) : "l"(v));
}

// ---------------------------------------------------------------------------
// Scratch (device globals; no allocation allowed)
// ---------------------------------------------------------------------------
__device__ float g_tmp1[BATCH * 64 * PLANE];      // conv1 out  (B,64,H,W)
__device__ float g_off [BATCH * 18 * PLANE];      // offsets    (B,18,H,W)
__device__ float g_tmp2[BATCH * CFEAT * PLANE];   // deform out (B,128,H,W)
__device__ float g_tmp3[BATCH * 64 * PLANE];      // fh conv1   (B,64,H,W)
__device__ float g_dwt [9 * CFEAT * CFEAT];       // dweight transposed [k][c][o]
__device__ float g_w1t [9 * 130 * 64];            // off_w1 transposed [kk][c][o]
__device__ float g_w3t [9 * 128 * 64];            // fh_w1  transposed [kk][c][o]

// ---------------------------------------------------------------------------
// Transpose deform weights: dweight (O=128, C=128, 3,3) -> dwt[k][c][o]
// ---------------------------------------------------------------------------
__global__ void wt_transpose_kernel(const float* __restrict__ dw) {
    int t = blockIdx.x * blockDim.x + threadIdx.x;
    if (t >= CFEAT * CFEAT * 9) return;
    int o  = t / (CFEAT * 9);
    int r  = t % (CFEAT * 9);
    int c  = r / 9;
    int kk = r % 9;
    g_dwt[(kk * CFEAT + c) * CFEAT + o] = dw[t];
}

// Transpose conv weights: w (64, CIN, 3,3) -> dst[(kk*CIN + c)*64 + o]
__global__ void conv_wt_transpose_kernel(const float* __restrict__ w,
                                         float* __restrict__ dst, int cin) {
    int t = blockIdx.x * blockDim.x + threadIdx.x;
    if (t >= 64 * cin * 9) return;
    int o  = t / (cin * 9);
    int r  = t % (cin * 9);
    int c  = r / 9;
    int kk = r % 9;
    dst[(kk * cin + c) * 64 + o] = w[t];
}

// ---------------------------------------------------------------------------
// 3x3 SAME conv v3, Cout = 64, f32x2, pre-transposed weights, CB=8,
// A values hoisted+packed once per cc (18 unique values reused over 9 taps).
// Block: 32(w) x 4(h) pixels, all 64 out channels. 256 threads:
//   wx = tid&31 (pixel w), og = tid>>5 (8 groups of 8 out channels)
// ---------------------------------------------------------------------------
template <int CINA, int CINB, bool RELU>
__global__ __launch_bounds__(256)
void conv3x3_c64_kernel(const float* __restrict__ inA, const float* __restrict__ inB,
                        const float* __restrict__ wt, const float* __restrict__ bias,
                        float* __restrict__ out) {
    constexpr int CIN = CINA + CINB;
    constexpr int CB = 8;
    __shared__ float s_in[CB][6][34];
    __shared__ float s_w[CB][9][64];   // [cc][kk][o]  -- o contiguous

    const int tid = threadIdx.x;
    const int wx = tid & 31;
    const int og = tid >> 5;
    const int w0 = blockIdx.x * 32;
    const int h0 = blockIdx.y * 4;
    const int b  = blockIdx.z;

    ull acc2[4][4];
#pragma unroll
    for (int i = 0; i < 4; i++)
#pragma unroll
        for (int j = 0; j < 4; j++) acc2[i][j] = 0ULL;

    for (int c0 = 0; c0 < CIN; c0 += CB) {
        // ---- stage input patch (CB channels, 6 rows x 34 cols, zero-padded)
        for (int i = tid; i < CB * 6 * 34; i += 256) {
            int cc  = i / 204;
            int rem = i % 204;
            int r   = rem / 34;
            int col = rem % 34;
            int c = c0 + cc;
            int y = h0 - 1 + r;
            int x = w0 - 1 + col;
            float v = 0.f;
            if (c < CIN && y >= 0 && y < HH && x >= 0 && x < WW) {
                v = (c < CINA) ? inA[((b * CINA + c) * HH + y) * WW + x]
                               : inB[((b * CINB + (c - CINA)) * HH + y) * WW + x];
            }
            s_in[cc][r][col] = v;
        }
        // ---- stage weights from transposed buffer (coalesced: o fastest)
        for (int i = tid; i < CB * 9 * 64; i += 256) {
            int o   = i & 63;
            int kk  = (i >> 6) % 9;
            int cc  = i / 576;
            int c = c0 + cc;
            s_w[cc][kk][o] = (c < CIN) ? wt[(kk * CIN + c) * 64 + o] : 0.f;
        }
        __syncthreads();

#pragma unroll
        for (int cc = 0; cc < CB; cc++) {
            // hoist + pack the 18 unique A values for this channel
            ull ad[6][3];
#pragma unroll
            for (int r = 0; r < 6; r++)
#pragma unroll
                for (int q = 0; q < 3; q++) {
                    float v = s_in[cc][r][wx + q];
                    ad[r][q] = pack2(v, v);
                }
#pragma unroll
            for (int kh = 0; kh < 3; kh++) {
#pragma unroll
                for (int kw = 0; kw < 3; kw++) {
                    const ulonglong2* bp =
                        (const ulonglong2*)&s_w[cc][kh * 3 + kw][og * 8];
                    ulonglong2 b01 = bp[0];
                    ulonglong2 b23 = bp[1];
                    ull bb[4] = {b01.x, b01.y, b23.x, b23.y};
#pragma unroll
                    for (int i = 0; i < 4; i++)
#pragma unroll
                        for (int j = 0; j < 4; j++)
                            fma2(acc2[i][j], ad[i + kh][kw], bb[j]);
                }
            }
        }
        __syncthreads();
    }

    // epilogue: lanes of acc2[i][j] are o = og*8 + 2j (+1)
#pragma unroll
    for (int j = 0; j < 4; j++) {
        int o0 = og * 8 + 2 * j;
        float b0 = bias[o0];
        float b1 = bias[o0 + 1];
#pragma unroll
        for (int i = 0; i < 4; i++) {
            float lo, hi;
            unpack2(acc2[i][j], lo, hi);
            float v0 = lo + b0;
            float v1 = hi + b1;
            if (RELU) { v0 = fmaxf(v0, 0.f); v1 = fmaxf(v1, 0.f); }
            out[((b * 64 + o0)     * HH + (h0 + i)) * WW + w0 + wx] = v0;
            out[((b * 64 + o0 + 1) * HH + (h0 + i)) * WW + w0 + wx] = v1;
        }
    }
}

// ---------------------------------------------------------------------------
// 3x3 SAME conv, CIN=64, small Cout (<=18), optional residual add.
// (known-good version)
// ---------------------------------------------------------------------------
template <int COUT, bool RES>
__global__ __launch_bounds__(256)
void conv3x3_small_kernel(const float* __restrict__ in, const float* __restrict__ wgt,
                          const float* __restrict__ bias, const float* __restrict__ res,
                          float* __restrict__ out) {
    constexpr int CIN = 64;
    constexpr int CB = 4;
    __shared__ float s_in[CB][10][34];
    __shared__ float s_w[CB][COUT * 9];

    const int tid = threadIdx.x;
    const int wx = tid & 31;
    const int hy = tid >> 5;
    const int w0 = blockIdx.x * 32;
    const int h0 = blockIdx.y * 8;
    const int b  = blockIdx.z;

    float acc[COUT];
#pragma unroll
    for (int o = 0; o < COUT; o++) acc[o] = 0.f;

    for (int c0 = 0; c0 < CIN; c0 += CB) {
        for (int i = tid; i < CB * 10 * 34; i += 256) {
            int cc  = i / 340;
            int rem = i % 340;
            int r   = rem / 34;
            int col = rem % 34;
            int y = h0 - 1 + r;
            int x = w0 - 1 + col;
            float v = 0.f;
            if (y >= 0 && y < HH && x >= 0 && x < WW)
                v = in[((b * CIN + c0 + cc) * HH + y) * WW + x];
            s_in[cc][r][col] = v;
        }
        for (int i = tid; i < CB * COUT * 9; i += 256) {
            int cc  = i / (COUT * 9);
            int rem = i % (COUT * 9);
            int o   = rem / 9;
            int kk  = rem % 9;
            s_w[cc][rem] = wgt[(o * CIN + (c0 + cc)) * 9 + kk];
        }
        __syncthreads();

#pragma unroll
        for (int cc = 0; cc < CB; cc++) {
#pragma unroll
            for (int kh = 0; kh < 3; kh++) {
#pragma unroll
                for (int kw = 0; kw < 3; kw++) {
                    float iv = s_in[cc][hy + kh][wx + kw];
#pragma unroll
                    for (int o = 0; o < COUT; o++)
                        acc[o] += iv * s_w[cc][o * 9 + kh * 3 + kw];
                }
            }
        }
        __syncthreads();
    }

#pragma unroll
    for (int o = 0; o < COUT; o++) {
        float v = acc[o] + bias[o];
        int oi = ((b * COUT + o) * HH + (h0 + hy)) * WW + w0 + wx;
        if (RES) v += res[oi];
        out[oi] = v;
    }
}

// ---------------------------------------------------------------------------
// Deformable 3x3 conv v4.
// Block = 64 pixels x all 128 out channels. 256 threads. smem = 112,128 B
// -> 2 CTAs/SM co-resident (hides sync/gather latency, removes wave tail).
// Per k: stage w[k] (128x128 o-contiguous), bilinear-gather 64px x 128c
// samples, then GEMM: per thread 4px x 8o, per c-step 1 LDS.128 (A) +
// 2 LDS.128 (B, warp-broadcast) + 4 pack + 16 fma2.
// ---------------------------------------------------------------------------
__global__ __launch_bounds__(256)
void deform_kernel(const float* __restrict__ feat, const float* __restrict__ offs,
                   const float* __restrict__ dbias, float* __restrict__ out) {
    extern __shared__ float smem[];
    float*          s_wk   = smem;                       // 16384 floats [c][o]
    float*          s_samp = smem + 16384;               //  8192 floats [c][px64]
    float*          s_wt   = smem + 16384 + 8192;        //  2304 floats [k][px][4]
    unsigned short* s_idx  = (unsigned short*)(smem + 16384 + 8192 + 2304); // 2304 u16

    const int tid = threadIdx.x;
    const int w0 = blockIdx.x * 64;
    const int h  = blockIdx.y;
    const int b  = blockIdx.z;

    // ---- precompute bilinear corners per (k, px)
    for (int task = tid; task < 576; task += 256) {
        int k  = task >> 6;
        int px = task & 63;
        int w = w0 + px;
        float offy = offs[((b * 18 + 2 * k)     * HH + h) * WW + w];
        float offx = offs[((b * 18 + 2 * k + 1) * HH + h) * WW + w];
        float fy = (float)(h + k / 3 - 1) + offy;
        float fx = (float)(w + k % 3 - 1) + offx;
        float y0f = floorf(fy), x0f = floorf(fx);
        float ly = fy - y0f, lx = fx - x0f;
        int y0 = (int)y0f, x0 = (int)x0f;
        float wts[4] = {(1.f - ly) * (1.f - lx), (1.f - ly) * lx,
                        ly * (1.f - lx),          ly * lx};
        int ys[4] = {y0, y0, y0 + 1, y0 + 1};
        int xs[4] = {x0, x0 + 1, x0, x0 + 1};
#pragma unroll
        for (int c4 = 0; c4 < 4; c4++) {
            bool valid = (ys[c4] >= 0) && (ys[c4] < HH) && (xs[c4] >= 0) && (xs[c4] < WW);
            s_idx[(k * 64 + px) * 4 + c4] =
                valid ? (unsigned short)(ys[c4] * WW + xs[c4]) : 0;
            s_wt [(k * 64 + px) * 4 + c4] = valid ? wts[c4] : 0.f;
        }
    }
    __syncthreads();

    ull acc2[4][4];
#pragma unroll
    for (int i = 0; i < 4; i++)
#pragma unroll
        for (int j = 0; j < 4; j++) acc2[i][j] = 0ULL;

    const int gpx = tid & 63;           // gather: pixel
    const int gc0 = (tid >> 6) * 32;    // gather: channel base (0/32/64/96)
    const int pxg = tid & 15;           // GEMM: 16 groups of 4 pixels
    const int og  = tid >> 4;           // GEMM: 16 groups of 8 out channels
    const float* fbase = feat + (size_t)b * CFEAT * PLANE;

    for (int k = 0; k < 9; k++) {
        // ---- stage weights for this k (contiguous [c][o], float4)
        const float4* wk4  = (const float4*)(g_dwt + k * CFEAT * CFEAT);
        float4*       swk4 = (float4*)s_wk;
#pragma unroll
        for (int i = 0; i < 16; i++) swk4[tid + 256 * i] = wk4[tid + 256 * i];

        // ---- bilinear gather: thread px=gpx, 32 channels starting at gc0
        const ushort4 iv = *(const ushort4*)&s_idx[(k * 64 + gpx) * 4];
        const float4  qv = *(const float4*)&s_wt[(k * 64 + gpx) * 4];
#pragma unroll 8
        for (int j = 0; j < 32; j++) {
            int c = gc0 + j;
            const float* fc = fbase + (size_t)c * PLANE;
            s_samp[c * 64 + gpx] =
                qv.x * fc[iv.x] + qv.y * fc[iv.y] + qv.z * fc[iv.z] + qv.w * fc[iv.w];
        }
        __syncthreads();

        // ---- 128(o) x 64(px) x 128(c) GEMM slice, 4px x 8o per thread
#pragma unroll 4
        for (int c = 0; c < CFEAT; c++) {
            float4 a = *(const float4*)(s_samp + c * 64 + pxg * 4);
            const ulonglong2* bp = (const ulonglong2*)(s_wk + c * CFEAT + og * 8);
            ulonglong2 b01 = bp[0];
            ulonglong2 b23 = bp[1];
            ull bb[4] = {b01.x, b01.y, b23.x, b23.y};
            ull ad[4];
            ad[0] = pack2(a.x, a.x); ad[1] = pack2(a.y, a.y);
            ad[2] = pack2(a.z, a.z); ad[3] = pack2(a.w, a.w);
#pragma unroll
            for (int i = 0; i < 4; i++)
#pragma unroll
                for (int j = 0; j < 4; j++) fma2(acc2[i][j], ad[i], bb[j]);
        }
        __syncthreads();
    }

    // ---- epilogue: acc2[i][j] lanes are o = og*8 + 2j (+1), px = pxg*4 + i
#pragma unroll
    for (int j = 0; j < 4; j++) {
        int o0 = og * 8 + 2 * j;
        float bv0 = dbias[o0];
        float bv1 = dbias[o0 + 1];
        float lo[4], hi[4];
#pragma unroll
        for (int i = 0; i < 4; i++) unpack2(acc2[i][j], lo[i], hi[i]);
        float* p0 = &out[(((size_t)b * CFEAT + o0)     * HH + h) * WW + w0 + pxg * 4];
        float* p1 = &out[(((size_t)b * CFEAT + o0 + 1) * HH + h) * WW + w0 + pxg * 4];
        *(float4*)p0 = make_float4(lo[0] + bv0, lo[1] + bv0, lo[2] + bv0, lo[3] + bv0);
        *(float4*)p1 = make_float4(hi[0] + bv1, hi[1] + bv1, hi[2] + bv1, hi[3] + bv1);
    }
}

// ---------------------------------------------------------------------------
// Launch
// ---------------------------------------------------------------------------
extern "C" void kernel_launch(void* const* d_in, const int* in_sizes, int n_in,
                              void* d_out, int out_size) {
    const float* feat    = (const float*)d_in[0];
    const float* flow    = (const float*)d_in[1];
    const float* off_w1  = (const float*)d_in[2];
    const float* off_b1  = (const float*)d_in[3];
    const float* off_w2  = (const float*)d_in[4];
    const float* off_b2  = (const float*)d_in[5];
    const float* dweight = (const float*)d_in[6];
    const float* dbias   = (const float*)d_in[7];
    const float* fh_w1   = (const float*)d_in[8];
    const float* fh_b1   = (const float*)d_in[9];
    const float* fh_w2   = (const float*)d_in[10];
    const float* fh_b2   = (const float*)d_in[11];
    float* out = (float*)d_out;

    float *tmp1, *off, *tmp2, *tmp3, *w1t, *w3t;
    cudaGetSymbolAddress((void**)&tmp1, g_tmp1);
    cudaGetSymbolAddress((void**)&off,  g_off);
    cudaGetSymbolAddress((void**)&tmp2, g_tmp2);
    cudaGetSymbolAddress((void**)&tmp3, g_tmp3);
    cudaGetSymbolAddress((void**)&w1t,  g_w1t);
    cudaGetSymbolAddress((void**)&w3t,  g_w3t);

    const int DEFORM_SMEM = (16384 + 8192 + 2304) * 4 + 2304 * 2;  // 112128 B
    cudaFuncSetAttribute(deform_kernel, cudaFuncAttributeMaxDynamicSharedMemorySize,
                         DEFORM_SMEM);

    // 0. weight transposes
    wt_transpose_kernel<<<(CFEAT * CFEAT * 9 + 255) / 256, 256>>>(dweight);
    conv_wt_transpose_kernel<<<(64 * 130 * 9 + 255) / 256, 256>>>(off_w1, w1t, 130);
    conv_wt_transpose_kernel<<<(64 * 128 * 9 + 255) / 256, 256>>>(fh_w1, w3t, 128);

    // 1. conv1: concat(feat, flow) (130ch) -> 64ch, relu
    conv3x3_c64_kernel<128, 2, true><<<dim3(4, 32, BATCH), 256>>>(
        feat, flow, w1t, off_b1, tmp1);

    // 2. conv2: 64 -> 18 (offsets)
    conv3x3_small_kernel<18, false><<<dim3(4, 16, BATCH), 256>>>(
        tmp1, off_w2, off_b2, nullptr, off);

    // 3. deformable conv: feat + offsets -> 128ch
    deform_kernel<<<dim3(2, 128, BATCH), 256, DEFORM_SMEM>>>(feat, off, dbias, tmp2);

    // 4. fh conv1: 128 -> 64, relu
    conv3x3_c64_kernel<128, 0, true><<<dim3(4, 32, BATCH), 256>>>(
        tmp2, tmp2, w3t, fh_b1, tmp3);

    // 5. fh conv2: 64 -> 2, + flow residual
    conv3x3_small_kernel<2, true><<<dim3(4, 16, BATCH), 256>>>(
        tmp3, fh_w2, fh_b2, flow, out);
}

// round 5
// speedup vs baseline: 1.3725x; 1.0370x over previous
#include <cuda_runtime.h>
#include <math.h>

// Problem constants
#define HH 128
#define WW 128
#define BATCH 2
#define CFEAT 128
#define PLANE (HH * WW)

typedef unsigned long long ull;

// ---------------------------------------------------------------------------
// f32x2 packed-FMA helpers (SASS FFMA2 — PTX-only)
// ---------------------------------------------------------------------------
__device__ __forceinline__ void fma2(ull& d, ull a, ull b) {
    asm("fma.rn.f32x2 %0, %1, %2, %3;" : "=l"(d) : "l"(a), "l"(b), "l"(d));
}
__device__ __forceinline__ ull pack2(float lo, float hi) {
    ull r;
    asm("mov.b64 %0, {%1, %2};" : "=l"(r) : "f"(lo), "f"(hi));
    return r;
}
__device__ __forceinline__ void unpack2(ull v, float& lo, float& hi) {
    asm("mov.b64 {%0, %1}, %2;" : "=f"(lo), "=f"(hi) : "l"(v));
}

// ---------------------------------------------------------------------------
// Scratch (device globals; no allocation allowed)
// ---------------------------------------------------------------------------
__device__ float g_tmp1[BATCH * 64 * PLANE];      // conv1 out  (B,64,H,W)
__device__ float g_off [BATCH * 18 * PLANE];      // offsets    (B,18,H,W)
__device__ float g_tmp2[BATCH * CFEAT * PLANE];   // deform out (B,128,H,W)
__device__ float g_tmp3[BATCH * 64 * PLANE];      // fh conv1   (B,64,H,W)
__device__ float g_dwt [9 * CFEAT * CFEAT];       // dweight transposed [k][c][o]
__device__ float g_w1t [9 * 130 * 64];            // off_w1 transposed [kk][c][o]
__device__ float g_w3t [9 * 128 * 64];            // fh_w1  transposed [kk][c][o]

// ---------------------------------------------------------------------------
// Weight transposes
// ---------------------------------------------------------------------------
__global__ void wt_transpose_kernel(const float* __restrict__ dw) {
    int t = blockIdx.x * blockDim.x + threadIdx.x;
    if (t >= CFEAT * CFEAT * 9) return;
    int o  = t / (CFEAT * 9);
    int r  = t % (CFEAT * 9);
    int c  = r / 9;
    int kk = r % 9;
    g_dwt[(kk * CFEAT + c) * CFEAT + o] = dw[t];
}

__global__ void conv_wt_transpose_kernel(const float* __restrict__ w,
                                         float* __restrict__ dst, int cin) {
    int t = blockIdx.x * blockDim.x + threadIdx.x;
    if (t >= 64 * cin * 9) return;
    int o  = t / (cin * 9);
    int r  = t % (cin * 9);
    int c  = r / 9;
    int kk = r % 9;
    dst[(kk * cin + c) * 64 + o] = w[t];
}

// ---------------------------------------------------------------------------
// 3x3 SAME conv v4, Cout = 64 split into two 32-channel halves per block.
// Block: 32(w) x 4(h) pixels x 32 out channels. 256 threads:
//   wx = tid&31, og = tid>>5 (8 groups of 4 out channels).
// grid = (8, 32, B): x = wtile*2 + ohalf.
// Software-pipelined: LDG(next)->regs before compute, STS after, ONE
// __syncthreads per channel-chunk. A stored in smem as duplicated {v,v}.
// ---------------------------------------------------------------------------
template <int CINA, int CINB, bool RELU>
__global__ __launch_bounds__(256)
void conv3x3_c64_kernel(const float* __restrict__ inA, const float* __restrict__ inB,
                        const float* __restrict__ wt, const float* __restrict__ bias,
                        float* __restrict__ out) {
    constexpr int CIN   = CINA + CINB;
    constexpr int CB    = 8;
    constexpr int NITER = (CIN + CB - 1) / CB;
    constexpr int NELI  = CB * 6 * 34;                 // 1632 input elems
    constexpr int NIN   = (NELI + 255) / 256;          // 7
    constexpr int NW    = (CB * 9 * 32) / 256;         // 9

    __shared__ float2 s_in[2][CB][6][34];   // duplicated {v,v}
    __shared__ float  s_w [2][CB][9][32];   // [cc][kk][o]

    const int tid   = threadIdx.x;
    const int wx    = tid & 31;
    const int og    = tid >> 5;
    const int wtile = blockIdx.x >> 1;
    const int ohalf = blockIdx.x & 1;
    const int w0 = wtile * 32;
    const int h0 = blockIdx.y * 4;
    const int b  = blockIdx.z;

    // ---- precompute c0-invariant staging indices
    int in_cc[NIN], in_poff[NIN];
    bool in_ok[NIN];
#pragma unroll
    for (int s = 0; s < NIN; s++) {
        int i = tid + s * 256;
        in_cc[s] = 0; in_poff[s] = 0; in_ok[s] = false;
        if (i < NELI) {
            int cc  = i / 204;
            int rem = i % 204;
            int r   = rem / 34;
            int col = rem % 34;
            int y = h0 - 1 + r;
            int x = w0 - 1 + col;
            in_cc[s] = cc;
            if (y >= 0 && y < HH && x >= 0 && x < WW) {
                in_ok[s]   = true;
                in_poff[s] = y * WW + x;
            }
        }
    }
    int w_off[NW], w_cc[NW];
#pragma unroll
    for (int s = 0; s < NW; s++) {
        int i  = tid + s * 256;
        int oo = i & 31;
        int kk = (i >> 5) % 9;
        int cc = i / 288;
        w_cc[s]  = cc;
        w_off[s] = (kk * CIN + cc) * 64 + ohalf * 32 + oo;
    }

    float vin[NIN], vw[NW];

    // ---- LDG for chunk `it` into registers
    auto ldg_chunk = [&](int it) {
        int c0 = it * CB;
#pragma unroll
        for (int s = 0; s < NIN; s++) {
            int c = c0 + in_cc[s];
            float v = 0.f;
            if (in_ok[s] && c < CIN) {
                if (CINB == 0 || c < CINA)
                    v = __ldg(&inA[(size_t)(b * CINA + c) * PLANE + in_poff[s]]);
                else
                    v = __ldg(&inB[(size_t)(b * CINB + (c - CINA)) * PLANE + in_poff[s]]);
            }
            vin[s] = v;
        }
#pragma unroll
        for (int s = 0; s < NW; s++) {
            int c = c0 + w_cc[s];
            vw[s] = (c < CIN) ? __ldg(&wt[(size_t)w_off[s] + (size_t)c0 * 64]) : 0.f;
        }
    };
    // ---- STS registers into buffer `buf`
    auto sts_chunk = [&](int buf) {
        float2* pi = &s_in[buf][0][0][0];
#pragma unroll
        for (int s = 0; s < NIN; s++) {
            int i = tid + s * 256;
            if (i < NELI) pi[i] = make_float2(vin[s], vin[s]);
        }
        float* pw = &s_w[buf][0][0][0];
#pragma unroll
        for (int s = 0; s < NW; s++) pw[tid + s * 256] = vw[s];
    };

    ull acc2[4][2];
#pragma unroll
    for (int i = 0; i < 4; i++) { acc2[i][0] = 0ULL; acc2[i][1] = 0ULL; }

    ldg_chunk(0);
    sts_chunk(0);
    __syncthreads();

    for (int it = 0; it < NITER; it++) {
        const int cur = it & 1;
        if (it + 1 < NITER) ldg_chunk(it + 1);

#pragma unroll
        for (int cc = 0; cc < CB; cc++) {
#pragma unroll
            for (int q = 0; q < 3; q++) {
                // column of 6 duplicated A values
                ull ad6[6];
#pragma unroll
                for (int r = 0; r < 6; r++)
                    ad6[r] = *(const ull*)&s_in[cur][cc][r][wx + q];
#pragma unroll
                for (int kh = 0; kh < 3; kh++) {
                    const ulonglong2 bb =
                        *(const ulonglong2*)&s_w[cur][cc][kh * 3 + q][og * 4];
#pragma unroll
                    for (int i = 0; i < 4; i++) {
                        fma2(acc2[i][0], ad6[i + kh], bb.x);
                        fma2(acc2[i][1], ad6[i + kh], bb.y);
                    }
                }
            }
        }

        if (it + 1 < NITER) sts_chunk(cur ^ 1);
        __syncthreads();
    }

    // ---- epilogue: acc2[i][j] lanes are o = ohalf*32 + og*4 + 2j (+1)
#pragma unroll
    for (int j = 0; j < 2; j++) {
        int o0 = ohalf * 32 + og * 4 + 2 * j;
        float b0 = bias[o0];
        float b1 = bias[o0 + 1];
#pragma unroll
        for (int i = 0; i < 4; i++) {
            float lo, hi;
            unpack2(acc2[i][j], lo, hi);
            float v0 = lo + b0;
            float v1 = hi + b1;
            if (RELU) { v0 = fmaxf(v0, 0.f); v1 = fmaxf(v1, 0.f); }
            out[((b * 64 + o0)     * HH + (h0 + i)) * WW + w0 + wx] = v0;
            out[((b * 64 + o0 + 1) * HH + (h0 + i)) * WW + w0 + wx] = v1;
        }
    }
}

// ---------------------------------------------------------------------------
// 3x3 SAME conv, CIN=64, small Cout (<=18), optional residual add.
// (known-good version)
// ---------------------------------------------------------------------------
template <int COUT, bool RES>
__global__ __launch_bounds__(256)
void conv3x3_small_kernel(const float* __restrict__ in, const float* __restrict__ wgt,
                          const float* __restrict__ bias, const float* __restrict__ res,
                          float* __restrict__ out) {
    constexpr int CIN = 64;
    constexpr int CB = 4;
    __shared__ float s_in[CB][10][34];
    __shared__ float s_w[CB][COUT * 9];

    const int tid = threadIdx.x;
    const int wx = tid & 31;
    const int hy = tid >> 5;
    const int w0 = blockIdx.x * 32;
    const int h0 = blockIdx.y * 8;
    const int b  = blockIdx.z;

    float acc[COUT];
#pragma unroll
    for (int o = 0; o < COUT; o++) acc[o] = 0.f;

    for (int c0 = 0; c0 < CIN; c0 += CB) {
        for (int i = tid; i < CB * 10 * 34; i += 256) {
            int cc  = i / 340;
            int rem = i % 340;
            int r   = rem / 34;
            int col = rem % 34;
            int y = h0 - 1 + r;
            int x = w0 - 1 + col;
            float v = 0.f;
            if (y >= 0 && y < HH && x >= 0 && x < WW)
                v = in[((b * CIN + c0 + cc) * HH + y) * WW + x];
            s_in[cc][r][col] = v;
        }
        for (int i = tid; i < CB * COUT * 9; i += 256) {
            int cc  = i / (COUT * 9);
            int rem = i % (COUT * 9);
            int o   = rem / 9;
            int kk  = rem % 9;
            s_w[cc][rem] = wgt[(o * CIN + (c0 + cc)) * 9 + kk];
        }
        __syncthreads();

#pragma unroll
        for (int cc = 0; cc < CB; cc++) {
#pragma unroll
            for (int kh = 0; kh < 3; kh++) {
#pragma unroll
                for (int kw = 0; kw < 3; kw++) {
                    float iv = s_in[cc][hy + kh][wx + kw];
#pragma unroll
                    for (int o = 0; o < COUT; o++)
                        acc[o] += iv * s_w[cc][o * 9 + kh * 3 + kw];
                }
            }
        }
        __syncthreads();
    }

#pragma unroll
    for (int o = 0; o < COUT; o++) {
        float v = acc[o] + bias[o];
        int oi = ((b * COUT + o) * HH + (h0 + hy)) * WW + w0 + wx;
        if (RES) v += res[oi];
        out[oi] = v;
    }
}

// ---------------------------------------------------------------------------
// Deformable 3x3 conv v4 (known-good from round 4).
// Block = 64 pixels x all 128 out channels. 256 threads. smem = 112,128 B
// -> 2 CTAs/SM co-resident.
// ---------------------------------------------------------------------------
__global__ __launch_bounds__(256)
void deform_kernel(const float* __restrict__ feat, const float* __restrict__ offs,
                   const float* __restrict__ dbias, float* __restrict__ out) {
    extern __shared__ float smem[];
    float*          s_wk   = smem;                       // 16384 floats [c][o]
    float*          s_samp = smem + 16384;               //  8192 floats [c][px64]
    float*          s_wt   = smem + 16384 + 8192;        //  2304 floats [k][px][4]
    unsigned short* s_idx  = (unsigned short*)(smem + 16384 + 8192 + 2304); // 2304 u16

    const int tid = threadIdx.x;
    const int w0 = blockIdx.x * 64;
    const int h  = blockIdx.y;
    const int b  = blockIdx.z;

    // ---- precompute bilinear corners per (k, px)
    for (int task = tid; task < 576; task += 256) {
        int k  = task >> 6;
        int px = task & 63;
        int w = w0 + px;
        float offy = offs[((b * 18 + 2 * k)     * HH + h) * WW + w];
        float offx = offs[((b * 18 + 2 * k + 1) * HH + h) * WW + w];
        float fy = (float)(h + k / 3 - 1) + offy;
        float fx = (float)(w + k % 3 - 1) + offx;
        float y0f = floorf(fy), x0f = floorf(fx);
        float ly = fy - y0f, lx = fx - x0f;
        int y0 = (int)y0f, x0 = (int)x0f;
        float wts[4] = {(1.f - ly) * (1.f - lx), (1.f - ly) * lx,
                        ly * (1.f - lx),          ly * lx};
        int ys[4] = {y0, y0, y0 + 1, y0 + 1};
        int xs[4] = {x0, x0 + 1, x0, x0 + 1};
#pragma unroll
        for (int c4 = 0; c4 < 4; c4++) {
            bool valid = (ys[c4] >= 0) && (ys[c4] < HH) && (xs[c4] >= 0) && (xs[c4] < WW);
            s_idx[(k * 64 + px) * 4 + c4] =
                valid ? (unsigned short)(ys[c4] * WW + xs[c4]) : 0;
            s_wt [(k * 64 + px) * 4 + c4] = valid ? wts[c4] : 0.f;
        }
    }
    __syncthreads();

    ull acc2[4][4];
#pragma unroll
    for (int i = 0; i < 4; i++)
#pragma unroll
        for (int j = 0; j < 4; j++) acc2[i][j] = 0ULL;

    const int gpx = tid & 63;           // gather: pixel
    const int gc0 = (tid >> 6) * 32;    // gather: channel base (0/32/64/96)
    const int pxg = tid & 15;           // GEMM: 16 groups of 4 pixels
    const int og  = tid >> 4;           // GEMM: 16 groups of 8 out channels
    const float* fbase = feat + (size_t)b * CFEAT * PLANE;

    for (int k = 0; k < 9; k++) {
        // ---- stage weights for this k (contiguous [c][o], float4)
        const float4* wk4  = (const float4*)(g_dwt + k * CFEAT * CFEAT);
        float4*       swk4 = (float4*)s_wk;
#pragma unroll
        for (int i = 0; i < 16; i++) swk4[tid + 256 * i] = wk4[tid + 256 * i];

        // ---- bilinear gather: thread px=gpx, 32 channels starting at gc0
        const ushort4 iv = *(const ushort4*)&s_idx[(k * 64 + gpx) * 4];
        const float4  qv = *(const float4*)&s_wt[(k * 64 + gpx) * 4];
#pragma unroll 8
        for (int j = 0; j < 32; j++) {
            int c = gc0 + j;
            const float* fc = fbase + (size_t)c * PLANE;
            s_samp[c * 64 + gpx] =
                qv.x * fc[iv.x] + qv.y * fc[iv.y] + qv.z * fc[iv.z] + qv.w * fc[iv.w];
        }
        __syncthreads();

        // ---- 128(o) x 64(px) x 128(c) GEMM slice, 4px x 8o per thread
#pragma unroll 4
        for (int c = 0; c < CFEAT; c++) {
            float4 a = *(const float4*)(s_samp + c * 64 + pxg * 4);
            const ulonglong2* bp = (const ulonglong2*)(s_wk + c * CFEAT + og * 8);
            ulonglong2 b01 = bp[0];
            ulonglong2 b23 = bp[1];
            ull bb[4] = {b01.x, b01.y, b23.x, b23.y};
            ull ad[4];
            ad[0] = pack2(a.x, a.x); ad[1] = pack2(a.y, a.y);
            ad[2] = pack2(a.z, a.z); ad[3] = pack2(a.w, a.w);
#pragma unroll
            for (int i = 0; i < 4; i++)
#pragma unroll
                for (int j = 0; j < 4; j++) fma2(acc2[i][j], ad[i], bb[j]);
        }
        __syncthreads();
    }

    // ---- epilogue: acc2[i][j] lanes are o = og*8 + 2j (+1), px = pxg*4 + i
#pragma unroll
    for (int j = 0; j < 4; j++) {
        int o0 = og * 8 + 2 * j;
        float bv0 = dbias[o0];
        float bv1 = dbias[o0 + 1];
        float lo[4], hi[4];
#pragma unroll
        for (int i = 0; i < 4; i++) unpack2(acc2[i][j], lo[i], hi[i]);
        float* p0 = &out[(((size_t)b * CFEAT + o0)     * HH + h) * WW + w0 + pxg * 4];
        float* p1 = &out[(((size_t)b * CFEAT + o0 + 1) * HH + h) * WW + w0 + pxg * 4];
        *(float4*)p0 = make_float4(lo[0] + bv0, lo[1] + bv0, lo[2] + bv0, lo[3] + bv0);
        *(float4*)p1 = make_float4(hi[0] + bv1, hi[1] + bv1, hi[2] + bv1, hi[3] + bv1);
    }
}

// ---------------------------------------------------------------------------
// Launch
// ---------------------------------------------------------------------------
extern "C" void kernel_launch(void* const* d_in, const int* in_sizes, int n_in,
                              void* d_out, int out_size) {
    const float* feat    = (const float*)d_in[0];
    const float* flow    = (const float*)d_in[1];
    const float* off_w1  = (const float*)d_in[2];
    const float* off_b1  = (const float*)d_in[3];
    const float* off_w2  = (const float*)d_in[4];
    const float* off_b2  = (const float*)d_in[5];
    const float* dweight = (const float*)d_in[6];
    const float* dbias   = (const float*)d_in[7];
    const float* fh_w1   = (const float*)d_in[8];
    const float* fh_b1   = (const float*)d_in[9];
    const float* fh_w2   = (const float*)d_in[10];
    const float* fh_b2   = (const float*)d_in[11];
    float* out = (float*)d_out;

    float *tmp1, *off, *tmp2, *tmp3, *w1t, *w3t;
    cudaGetSymbolAddress((void**)&tmp1, g_tmp1);
    cudaGetSymbolAddress((void**)&off,  g_off);
    cudaGetSymbolAddress((void**)&tmp2, g_tmp2);
    cudaGetSymbolAddress((void**)&tmp3, g_tmp3);
    cudaGetSymbolAddress((void**)&w1t,  g_w1t);
    cudaGetSymbolAddress((void**)&w3t,  g_w3t);

    const int DEFORM_SMEM = (16384 + 8192 + 2304) * 4 + 2304 * 2;  // 112128 B
    cudaFuncSetAttribute(deform_kernel, cudaFuncAttributeMaxDynamicSharedMemorySize,
                         DEFORM_SMEM);

    // 0. weight transposes
    wt_transpose_kernel<<<(CFEAT * CFEAT * 9 + 255) / 256, 256>>>(dweight);
    conv_wt_transpose_kernel<<<(64 * 130 * 9 + 255) / 256, 256>>>(off_w1, w1t, 130);
    conv_wt_transpose_kernel<<<(64 * 128 * 9 + 255) / 256, 256>>>(fh_w1, w3t, 128);

    // 1. conv1: concat(feat, flow) (130ch) -> 64ch, relu  (grid.x = wtile*2+ohalf)
    conv3x3_c64_kernel<128, 2, true><<<dim3(8, 32, BATCH), 256>>>(
        feat, flow, w1t, off_b1, tmp1);

    // 2. conv2: 64 -> 18 (offsets)
    conv3x3_small_kernel<18, false><<<dim3(4, 16, BATCH), 256>>>(
        tmp1, off_w2, off_b2, nullptr, off);

    // 3. deformable conv: feat + offsets -> 128ch
    deform_kernel<<<dim3(2, 128, BATCH), 256, DEFORM_SMEM>>>(feat, off, dbias, tmp2);

    // 4. fh conv1: 128 -> 64, relu
    conv3x3_c64_kernel<128, 0, true><<<dim3(8, 32, BATCH), 256>>>(
        tmp2, tmp2, w3t, fh_b1, tmp3);

    // 5. fh conv2: 64 -> 2, + flow residual
    conv3x3_small_kernel<2, true><<<dim3(4, 16, BATCH), 256>>>(
        tmp3, fh_w2, fh_b2, flow, out);
}